// round 10
// baseline (speedup 1.0000x reference)
#include <cuda_runtime.h>
#include <cuda_bf16.h>
#include <cuda_fp16.h>
#include <cstdint>

// PowerSoftmax attention, int8-split QK + fp16 PV, with pre-pass kernels.
//   S = (Q K^T)/8 ; P = S^2 ; O = (P / (rowsum(P)+1e-6)) V
// 64 heads of [2048, 64] fp32.
//
// Pre-pass 1: per-row int8 2-term quantization of Q and K (scale = rowmax/127,
//             lo term = residual/ (s/254)), written as ready-to-use MMA
//             fragment images + per-row scales.
// Pre-pass 2: V -> fp16, transposed Vt[d][kv] swizzled image (ldmatrix-ready).
// Main: per CTA 128 q-rows, stream kv in 128-row tiles; QK via
//       mma.m16n8k32.s8 (3 cross products, 2 s32 accumulators), PV via
//       mma.m16n8k16.f16. Double-buffered cp.async tile fill.

#define NQ       2048
#define DDIM     64
#define BM       128
#define BKV      128
#define NITER    (NQ / BKV)
#define NTHREADS 256
#define NHEADS   64

// image geometry
#define KTILE    16896               // 8KB hi + 8KB lo + 512B scales
#define KHEAD    (16 * KTILE)
#define QTILE    16384               // 8KB hi + 8KB lo
#define QHEAD    (16 * QTILE)
#define VTILE    16384
#define VHEAD    (16 * VTILE)

__device__ unsigned char g_qimg[(size_t)NHEADS * QHEAD];
__device__ unsigned char g_kimg[(size_t)NHEADS * KHEAD];
__device__ unsigned char g_vimg[(size_t)NHEADS * VHEAD];
__device__ float         g_sa[(size_t)NHEADS * NQ];

// main-kernel smem: two buffers of [Khi 8K | Klo 8K | SB 512B | V 16K]
#define BUFSZ     33280
#define BK_LO     8192
#define B_SB      16384
#define B_V       16896
#define SMEM_BYTES (2 * BUFSZ)       // 66560

// Vt tile: [64 rows][128 kv x 2B = 256B], swizzled
__device__ __forceinline__ uint32_t sw_v(int row, int cb) {
    return (uint32_t)(row * 256 + (cb ^ ((row & 7) << 4)));
}

__device__ __forceinline__ void ldsm_x4(uint32_t* r, uint32_t addr) {
    asm volatile("ldmatrix.sync.aligned.m8n8.x4.shared.b16 {%0,%1,%2,%3}, [%4];"
                 : "=r"(r[0]), "=r"(r[1]), "=r"(r[2]), "=r"(r[3]) : "r"(addr));
}
__device__ __forceinline__ void lds64(uint32_t* r, uint32_t addr) {
    asm volatile("ld.shared.v2.u32 {%0,%1}, [%2];"
                 : "=r"(r[0]), "=r"(r[1]) : "r"(addr));
}
__device__ __forceinline__ void lds64f(float* r, uint32_t addr) {
    asm volatile("ld.shared.v2.f32 {%0,%1}, [%2];"
                 : "=f"(r[0]), "=f"(r[1]) : "r"(addr));
}
__device__ __forceinline__ void mma_f16(float* c, const uint32_t* a, const uint32_t* b) {
    asm volatile("mma.sync.aligned.m16n8k16.row.col.f32.f16.f16.f32 "
                 "{%0,%1,%2,%3}, {%4,%5,%6,%7}, {%8,%9}, {%0,%1,%2,%3};"
                 : "+f"(c[0]), "+f"(c[1]), "+f"(c[2]), "+f"(c[3])
                 : "r"(a[0]), "r"(a[1]), "r"(a[2]), "r"(a[3]), "r"(b[0]), "r"(b[1]));
}
__device__ __forceinline__ void mma_s8(int* c, const uint32_t* a, const uint32_t* b) {
    asm volatile("mma.sync.aligned.m16n8k32.row.col.s32.s8.s8.s32 "
                 "{%0,%1,%2,%3}, {%4,%5,%6,%7}, {%8,%9}, {%0,%1,%2,%3};"
                 : "+r"(c[0]), "+r"(c[1]), "+r"(c[2]), "+r"(c[3])
                 : "r"(a[0]), "r"(a[1]), "r"(a[2]), "r"(a[3]), "r"(b[0]), "r"(b[1]));
}
__device__ __forceinline__ void cp16(uint32_t dst, const void* src) {
    asm volatile("cp.async.cg.shared.global [%0], [%1], 16;" :: "r"(dst), "l"(src));
}
#define CP_COMMIT() asm volatile("cp.async.commit_group;" ::: "memory")
#define CP_WAIT0()  asm volatile("cp.async.wait_group 0;" ::: "memory")

// ---------------------------------------------------------------------------
// Pre-pass 1: quantize Q and K rows -> int8 hi/lo fragment images + scales
// one thread per row. gid: [which(2)][head(64)][row(2048)]
// ---------------------------------------------------------------------------
__global__ __launch_bounds__(256)
void prepass_qk(const float* __restrict__ Q, const float* __restrict__ K) {
    int gid   = blockIdx.x * 256 + threadIdx.x;      // 0 .. 262143
    int which = gid >> 17;                           // 0 = Q, 1 = K
    int rowg  = gid & 131071;
    int head  = rowg >> 11;
    int row   = rowg & 2047;
    const float4* src =
        (const float4*)(((which ? K : Q) + ((size_t)head * NQ + row) * DDIM));

    // pass 1: row max
    float mx = 0.f;
    #pragma unroll
    for (int i = 0; i < 16; ++i) {
        float4 v = src[i];
        mx = fmaxf(mx, fmaxf(fmaxf(fabsf(v.x), fabsf(v.y)),
                             fmaxf(fabsf(v.z), fabsf(v.w))));
    }
    float s    = fmaxf(mx, 1e-20f) * (1.f / 127.f);
    float inv  = 1.f / s;
    float inv2 = 254.f * inv;

    int tile = row >> 7;
    int nn   = row & 127;

    unsigned char* base;
    if (which) {   // K: B-fragment image. h = nn>>6, nb=(nn>>3)&7, g=nn&7
        int h = nn >> 6, nb = (nn >> 3) & 7, g = nn & 7;
        base = g_kimg + (size_t)head * KHEAD + (size_t)tile * KTILE;
        *(float*)(base + B_SB + nn * 4) = s;
        #pragma unroll
        for (int i = 0; i < 16; ++i) {               // k = 4i .. 4i+3
            float4 v = src[i];
            int c  = i & 3;
            int kh = (i >> 2) & 1;
            int ks = i >> 3;
            int h0 = (int)rintf(v.x * inv), h1 = (int)rintf(v.y * inv);
            int h2 = (int)rintf(v.z * inv), h3 = (int)rintf(v.w * inv);
            int l0 = (int)rintf((v.x - (float)h0 * s) * inv2);
            int l1 = (int)rintf((v.y - (float)h1 * s) * inv2);
            int l2 = (int)rintf((v.z - (float)h2 * s) * inv2);
            int l3 = (int)rintf((v.w - (float)h3 * s) * inv2);
            uint32_t wh = (uint32_t)(h0 & 255) | ((uint32_t)(h1 & 255) << 8) |
                          ((uint32_t)(h2 & 255) << 16) | ((uint32_t)(h3 & 255) << 24);
            uint32_t wl = (uint32_t)(l0 & 255) | ((uint32_t)(l1 & 255) << 8) |
                          ((uint32_t)(l2 & 255) << 16) | ((uint32_t)(l3 & 255) << 24);
            uint32_t off = (uint32_t)((((h * 2 + ks) * 8 + nb) * 32 + g * 4 + c) * 8
                                      + kh * 4);
            *(uint32_t*)(base + off)        = wh;
            *(uint32_t*)(base + BK_LO + off) = wl;
        }
    } else {       // Q: A-fragment image + scale
        g_sa[(size_t)head * NQ + row] = s;
        int rr = nn;
        int wid = rr >> 4, t16 = rr & 15;
        int g = t16 & 7, half = t16 >> 3;
        base = g_qimg + (size_t)head * QHEAD + (size_t)tile * QTILE;
        #pragma unroll
        for (int i = 0; i < 16; ++i) {
            float4 v = src[i];
            int c  = i & 3;
            int kh = (i >> 2) & 1;
            int ks = i >> 3;
            int h0 = (int)rintf(v.x * inv), h1 = (int)rintf(v.y * inv);
            int h2 = (int)rintf(v.z * inv), h3 = (int)rintf(v.w * inv);
            int l0 = (int)rintf((v.x - (float)h0 * s) * inv2);
            int l1 = (int)rintf((v.y - (float)h1 * s) * inv2);
            int l2 = (int)rintf((v.z - (float)h2 * s) * inv2);
            int l3 = (int)rintf((v.w - (float)h3 * s) * inv2);
            uint32_t wh = (uint32_t)(h0 & 255) | ((uint32_t)(h1 & 255) << 8) |
                          ((uint32_t)(h2 & 255) << 16) | ((uint32_t)(h3 & 255) << 24);
            uint32_t wl = (uint32_t)(l0 & 255) | ((uint32_t)(l1 & 255) << 8) |
                          ((uint32_t)(l2 & 255) << 16) | ((uint32_t)(l3 & 255) << 24);
            int reg = half + kh * 2;                  // a0..a3
            uint32_t off = (uint32_t)(((wid * 2 + ks) * 32 + g * 4 + c) * 16 + reg * 4);
            *(uint32_t*)(base + off)        = wh;
            *(uint32_t*)(base + 8192 + off) = wl;
        }
    }
}

// ---------------------------------------------------------------------------
// Pre-pass 2: V -> fp16 Vt[d][kv] swizzled image. Block per (head, tile).
// ---------------------------------------------------------------------------
__global__ __launch_bounds__(256)
void prepass_v(const float* __restrict__ V) {
    __shared__ float raw[BKV * DDIM];                // 32 KB
    int head = blockIdx.x >> 4;
    int tile = blockIdx.x & 15;
    int tid  = threadIdx.x;

    const float4* src = (const float4*)(V + ((size_t)head * NQ + (size_t)tile * BKV) * DDIM);
    #pragma unroll
    for (int p = 0; p < 8; ++p)
        ((float4*)raw)[tid + p * 256] = src[tid + p * 256];
    __syncthreads();

    unsigned char* dst = g_vimg + (size_t)head * VHEAD + (size_t)tile * VTILE;
    int d   = tid & 63;
    int kvq = tid >> 6;
    #pragma unroll
    for (int i = 0; i < 8; ++i) {
        int kv = kvq * 32 + i * 4;
        float x0 = raw[(kv + 0) * DDIM + d];
        float x1 = raw[(kv + 1) * DDIM + d];
        float x2 = raw[(kv + 2) * DDIM + d];
        float x3 = raw[(kv + 3) * DDIM + d];
        __half2 ha = __floats2half2_rn(x0, x1);
        __half2 hb = __floats2half2_rn(x2, x3);
        uint2 u;
        u.x = *(uint32_t*)&ha;
        u.y = *(uint32_t*)&hb;
        *(uint2*)(dst + sw_v(d, kv * 2)) = u;
    }
}

// ---------------------------------------------------------------------------
// Main kernel
// ---------------------------------------------------------------------------
__global__ __launch_bounds__(NTHREADS, 2)
void power_attn_i8(float* __restrict__ O) {
    extern __shared__ char sm[];
    const uint32_t smb = (uint32_t)__cvta_generic_to_shared(sm);

    const int tid  = threadIdx.x;
    const int lane = tid & 31;
    const int wid  = tid >> 5;
    const int mr   = wid * 16;
    const int g    = lane >> 2;

    const int head = blockIdx.y;
    const int qt   = blockIdx.x;

    // ---- prologue: prefetch tile 0, load Q fragments + scales ----
    const unsigned char* kimg0 = g_kimg + (size_t)head * KHEAD;
    const unsigned char* vimg0 = g_vimg + (size_t)head * VHEAD;
    {
        #pragma unroll
        for (int p = 0; p < 8; ++p) {
            int idx = tid + p * NTHREADS;            // 0..2047
            if (idx < 1056) cp16(smb + idx * 16, kimg0 + idx * 16);
            else            cp16(smb + B_V + (idx - 1056) * 16, vimg0 + (idx - 1056) * 16);
        }
        if (tid < 32) {
            int rem = 992 + tid;
            cp16(smb + B_V + rem * 16, vimg0 + rem * 16);
        }
        CP_COMMIT();
    }

    uint32_t Qh[2][4], Ql[2][4];
    {
        const uint4* qf = (const uint4*)(g_qimg + (size_t)head * QHEAD + (size_t)qt * QTILE);
        #pragma unroll
        for (int ks = 0; ks < 2; ++ks) {
            uint4 a = qf[(wid * 2 + ks) * 32 + lane];
            Qh[ks][0] = a.x; Qh[ks][1] = a.y; Qh[ks][2] = a.z; Qh[ks][3] = a.w;
            uint4 b = qf[512 + (wid * 2 + ks) * 32 + lane];   // +8192B
            Ql[ks][0] = b.x; Ql[ks][1] = b.y; Ql[ks][2] = b.z; Ql[ks][3] = b.w;
        }
    }
    float SA0p, SA1p;
    {
        const float* sa = g_sa + (size_t)head * NQ + (size_t)qt * BM;
        SA0p = sa[mr + g]     * 0.125f;
        SA1p = sa[mr + g + 8] * 0.125f;
    }

    float OC[8][4];
    #pragma unroll
    for (int d = 0; d < 8; ++d)
        #pragma unroll
        for (int r = 0; r < 4; ++r) OC[d][r] = 0.f;
    float rs0 = 0.f, rs1 = 0.f;

    const int bx_row = (lane & 7) + ((lane >> 4) << 3);   // V ldmatrix x4
    const int bx_cbo = ((lane >> 3) & 1) << 4;
    const float C254 = 1.f / 254.f;

    for (int nt = 0; nt < NITER; ++nt) {
        const uint32_t buf = smb + (uint32_t)(nt & 1) * BUFSZ;
        CP_WAIT0();
        __syncthreads();          // buffer ready; other buffer free for prefetch

        if (nt + 1 < NITER) {
            const uint32_t nb_buf = smb + (uint32_t)((nt + 1) & 1) * BUFSZ;
            const unsigned char* kimg = kimg0 + (size_t)(nt + 1) * KTILE;
            const unsigned char* vimg = vimg0 + (size_t)(nt + 1) * VTILE;
            #pragma unroll
            for (int p = 0; p < 8; ++p) {
                int idx = tid + p * NTHREADS;
                if (idx < 1056) cp16(nb_buf + idx * 16, kimg + idx * 16);
                else            cp16(nb_buf + B_V + (idx - 1056) * 16, vimg + (idx - 1056) * 16);
            }
            if (tid < 32) {
                int rem = 992 + tid;
                cp16(nb_buf + B_V + rem * 16, vimg + rem * 16);
            }
            CP_COMMIT();
        }

        #pragma unroll
        for (int h = 0; h < 2; ++h) {
            #pragma unroll
            for (int pc = 0; pc < 2; ++pc) {          // 4 n-blocks per chunk
                int accA[4][4], accB[4][4];
                #pragma unroll
                for (int j = 0; j < 4; ++j)
                    #pragma unroll
                    for (int r = 0; r < 4; ++r) { accA[j][r] = 0; accB[j][r] = 0; }

                #pragma unroll
                for (int ks = 0; ks < 2; ++ks) {
                    #pragma unroll
                    for (int j = 0; j < 4; ++j) {
                        int nb = pc * 4 + j;
                        uint32_t off = buf + (uint32_t)((((h * 2 + ks) * 8 + nb) * 32 + lane) * 8);
                        uint32_t bh[2], bl[2];
                        lds64(bh, off);
                        lds64(bl, off + BK_LO);
                        mma_s8(accA[j], Qh[ks], bh);
                        mma_s8(accB[j], Qh[ks], bl);
                        mma_s8(accB[j], Ql[ks], bh);
                    }
                }

                // ---- epilogue: scale, square, pack fp16 P, rowsum ----
                uint32_t P[2][4];
                #pragma unroll
                for (int j = 0; j < 4; ++j) {
                    int col0 = h * 64 + pc * 32 + j * 8 + (lane & 3) * 2;
                    float sb[2];
                    lds64f(sb, buf + B_SB + (uint32_t)(col0 * 4));
                    float m00 = SA0p * sb[0], m01 = SA0p * sb[1];
                    float m10 = SA1p * sb[0], m11 = SA1p * sb[1];
                    float e00 = ((float)accA[j][0] + (float)accB[j][0] * C254) * m00;
                    float e01 = ((float)accA[j][1] + (float)accB[j][1] * C254) * m01;
                    float e10 = ((float)accA[j][2] + (float)accB[j][2] * C254) * m10;
                    float e11 = ((float)accA[j][3] + (float)accB[j][3] * C254) * m11;
                    __half2 h0 = __floats2half2_rn(e00 * e00, e01 * e01);
                    __half2 h1 = __floats2half2_rn(e10 * e10, e11 * e11);
                    float2 f0 = __half22float2(h0);
                    float2 f1 = __half22float2(h1);
                    rs0 += f0.x + f0.y;
                    rs1 += f1.x + f1.y;
                    P[j >> 1][(j & 1) * 2 + 0] = *(uint32_t*)&h0;
                    P[j >> 1][(j & 1) * 2 + 1] = *(uint32_t*)&h1;
                }

                // ---- O += P V ----
                #pragma unroll
                for (int kk = 0; kk < 2; ++kk) {
                    int kvb = (h * 64 + pc * 32 + kk * 16) * 2 + bx_cbo;
                    #pragma unroll
                    for (int dp = 0; dp < 4; ++dp) {
                        uint32_t Bv[4];
                        ldsm_x4(Bv, buf + B_V + sw_v(dp * 16 + bx_row, kvb));
                        mma_f16(OC[2 * dp],     P[kk], Bv + 0);
                        mma_f16(OC[2 * dp + 1], P[kk], Bv + 2);
                    }
                }
            }
        }
    }

    // ---- rowsum reduce + store ----
    rs0 += __shfl_xor_sync(0xFFFFFFFF, rs0, 1);
    rs0 += __shfl_xor_sync(0xFFFFFFFF, rs0, 2);
    rs1 += __shfl_xor_sync(0xFFFFFFFF, rs1, 1);
    rs1 += __shfl_xor_sync(0xFFFFFFFF, rs1, 2);
    const float inv0 = 1.0f / (rs0 + 1e-6f);
    const float inv1 = 1.0f / (rs1 + 1e-6f);

    {
        const int row0 = mr + g;
        float* ob = O + ((size_t)head * NQ + (size_t)qt * BM + row0) * DDIM;
        #pragma unroll
        for (int db = 0; db < 8; ++db) {
            int col = db * 8 + (lane & 3) * 2;
            float2 t0 = make_float2(OC[db][0] * inv0, OC[db][1] * inv0);
            float2 t1 = make_float2(OC[db][2] * inv1, OC[db][3] * inv1);
            *(float2*)(ob + col) = t0;
            *(float2*)(ob + 8 * DDIM + col) = t1;
        }
    }
}

extern "C" void kernel_launch(void* const* d_in, const int* in_sizes, int n_in,
                              void* d_out, int out_size) {
    const float* q = (const float*)d_in[0];
    const float* k = (const float*)d_in[1];
    const float* v = (const float*)d_in[2];
    float* o = (float*)d_out;

    cudaFuncSetAttribute(power_attn_i8,
                         cudaFuncAttributeMaxDynamicSharedMemorySize, SMEM_BYTES);

    prepass_qk<<<(2 * NHEADS * NQ) / 256, 256>>>(q, k);
    prepass_v<<<NHEADS * 16, 256>>>(v);

    dim3 grid(NQ / BM, NHEADS);
    power_attn_i8<<<grid, NTHREADS, SMEM_BYTES>>>(o);
}